// round 9
// baseline (speedup 1.0000x reference)
#include <cuda_runtime.h>

#define BB 256   // batch
#define SS 512   // seq len
#define TT 128   // tags

__device__ float g_partial[BB];

__device__ __forceinline__ float f32x2_hsum(unsigned long long v) {
    float lo, hi;
    asm("mov.b64 {%0, %1}, %2;" : "=f"(lo), "=f"(hi) : "l"(v));
    return lo + hi;
}

__global__ __launch_bounds__(TT, 2) void crf_main(
    const float* __restrict__ em,      // [B, S, T]
    const int*   __restrict__ tagw,    // raw 32-bit words of tags (int32 or int64)
    const float* __restrict__ trans)   // [T, T]
{
    const int b = blockIdx.x;
    const int j = threadIdx.x;          // tag column owned by this thread
    const int wid = j >> 5;
    const int lane = j & 31;

    __shared__ __align__(16) float sm_a0[TT], sm_a1[TT];   // double-buffered exp(alpha - m_w)
    __shared__ __align__(16) float sm_mw0[4], sm_mw1[4];   // per-warp baselines
    __shared__ float smx[4], sms[4], smg[4];

    // ---- detect tags dtype: int64 -> odd 32-bit words are all-zero high halves ----
    int orv = 0;
    #pragma unroll
    for (int q = 1; q < 64; q += 2) orv |= tagw[q];
    const int stride = (orv == 0) ? 2 : 1;
    const int* tb = tagw + b * SS * stride;

    // ---- register-resident E column j: Ep[k] = (exp(tr[2k][j]), exp(tr[2k+1][j])) ----
    unsigned long long Ep[TT / 2];
    #pragma unroll
    for (int k = 0; k < TT / 2; k++) {
        float e0 = __expf(trans[(2 * k) * TT + j]);
        float e1 = __expf(trans[(2 * k + 1) * TT + j]);
        unsigned long long pk;
        asm("mov.b64 %0, {%1, %2};" : "=l"(pk) : "f"(e0), "f"(e1));
        Ep[k] = pk;
    }

    const float* emb = em + (size_t)b * SS * TT;

    // ---- t = 0 ----
    float alpha = emb[j];
    const int tag0 = tb[0];
    float gold = (j == tag0) ? alpha : 0.0f;

    // depth-3 prefetch pipeline (branchless clamped indices; over-end values unused)
    float ec0 = __ldg(emb + 1 * TT + j);
    float ec1 = __ldg(emb + 2 * TT + j);
    float ec2 = __ldg(emb + 3 * TT + j);
    int   tg0 = __ldg(tb + 1 * stride);
    int   tg1 = __ldg(tb + 2 * stride);
    int   tg2 = __ldg(tb + 3 * stride);
    // gold transitions issued 2 steps ahead of consumption
    float trp0 = __ldg(trans + tag0 * TT + tg0);   // step 1: trans[tags[0]][tags[1]]
    float trp1 = __ldg(trans + tg0  * TT + tg1);   // step 2: trans[tags[1]][tags[2]]

    float* aw  = sm_a0;  float* ar  = sm_a1;
    float* mww = sm_mw0; float* mwr = sm_mw1;

    for (int t = 1; t < SS; t++) {
        // depth-3 loads for step t+3 (clamped; unconditional LDGs batch better)
        const int tc = (t + 3 < SS) ? (t + 3) : (SS - 1);
        float e3  = __ldg(emb + tc * TT + j);
        int   tg3 = __ldg(tb + tc * stride);
        // gold transition for step t+2: trans[tags[t+1]][tags[t+2]]
        float trp2 = __ldg(trans + tg1 * TT + tg2);

        // per-warp baseline (no smem round trip before the rebase exp)
        const float mw = __shfl_sync(0xffffffffu, alpha, 0);
        aw[j] = __expf(alpha - mw);
        if (lane == 0) mww[wid] = mw;
        __syncthreads();   // single barrier/step; buffer swap handles WAR

        // baselines as one LDS.128 issued up front (latency hides under FMA block)
        const float4 mv = *(const float4*)mww;

        // s_j = sum_i a_i * E[i,j]; partials grouped by producer warp of i
        unsigned long long acc0 = 0ull, acc1 = 0ull, acc2 = 0ull, acc3 = 0ull;
        const ulonglong2* ap = (const ulonglong2*)aw;   // 16B broadcast loads
        #pragma unroll
        for (int q = 0; q < 8; q++) {
            ulonglong2 aA = ap[q];        // i in [ 0, 32)
            ulonglong2 aB = ap[8  + q];   // i in [32, 64)
            ulonglong2 aC = ap[16 + q];   // i in [64, 96)
            ulonglong2 aD = ap[24 + q];   // i in [96,128)
            asm("fma.rn.f32x2 %0, %1, %2, %0;" : "+l"(acc0) : "l"(Ep[ 0 + 2*q]), "l"(aA.x));
            asm("fma.rn.f32x2 %0, %1, %2, %0;" : "+l"(acc1) : "l"(Ep[16 + 2*q]), "l"(aB.x));
            asm("fma.rn.f32x2 %0, %1, %2, %0;" : "+l"(acc2) : "l"(Ep[32 + 2*q]), "l"(aC.x));
            asm("fma.rn.f32x2 %0, %1, %2, %0;" : "+l"(acc3) : "l"(Ep[48 + 2*q]), "l"(aD.x));
            asm("fma.rn.f32x2 %0, %1, %2, %0;" : "+l"(acc0) : "l"(Ep[ 1 + 2*q]), "l"(aA.y));
            asm("fma.rn.f32x2 %0, %1, %2, %0;" : "+l"(acc1) : "l"(Ep[17 + 2*q]), "l"(aB.y));
            asm("fma.rn.f32x2 %0, %1, %2, %0;" : "+l"(acc2) : "l"(Ep[33 + 2*q]), "l"(aC.y));
            asm("fma.rn.f32x2 %0, %1, %2, %0;" : "+l"(acc3) : "l"(Ep[49 + 2*q]), "l"(aD.y));
        }

        // combine warp-group partials with scale factors relative to warp 0's baseline
        const float sc1 = __expf(mv.y - mv.x);
        const float sc2 = __expf(mv.z - mv.x);
        const float sc3 = __expf(mv.w - mv.x);
        float s = f32x2_hsum(acc0);
        s = fmaf(f32x2_hsum(acc1), sc1, s);
        s = fmaf(f32x2_hsum(acc2), sc2, s);
        s = fmaf(f32x2_hsum(acc3), sc3, s);

        alpha = mv.x + __logf(s) + ec0;

        // gold: emission at t (thread owning tags[t]) + transition tags[t-1]->tags[t]
        if (j == tg0) gold += ec0 + trp0;

        // rotate pipelines and swap buffers
        ec0 = ec1; ec1 = ec2; ec2 = e3;
        tg0 = tg1; tg1 = tg2; tg2 = tg3;
        trp0 = trp1; trp1 = trp2;
        float* tmp;
        tmp = aw;  aw  = ar;  ar  = tmp;
        tmp = mww; mww = mwr; mwr = tmp;
    }

    // ---- final logsumexp over alpha (exact block max) + gold reduction ----
    float wm = alpha;
    #pragma unroll
    for (int o = 16; o; o >>= 1) wm = fmaxf(wm, __shfl_xor_sync(0xffffffffu, wm, o));
    if (lane == 0) smx[wid] = wm;
    __syncthreads();
    const float bm = fmaxf(fmaxf(smx[0], smx[1]), fmaxf(smx[2], smx[3]));

    float ex = __expf(alpha - bm);
    float wg = gold;
    #pragma unroll
    for (int o = 16; o; o >>= 1) {
        ex += __shfl_xor_sync(0xffffffffu, ex, o);
        wg += __shfl_xor_sync(0xffffffffu, wg, o);
    }
    if (lane == 0) { sms[wid] = ex; smg[wid] = wg; }
    __syncthreads();
    if (j == 0) {
        const float ssum = (sms[0] + sms[1]) + (sms[2] + sms[3]);
        const float gsum = (smg[0] + smg[1]) + (smg[2] + smg[3]);
        g_partial[b] = (bm + __logf(ssum)) - gsum;
    }
}

__global__ __launch_bounds__(BB) void crf_reduce(float* __restrict__ out)
{
    __shared__ float sm[BB];
    const int tid = threadIdx.x;
    sm[tid] = g_partial[tid];
    __syncthreads();
    #pragma unroll
    for (int s = BB / 2; s > 0; s >>= 1) {
        if (tid < s) sm[tid] += sm[tid + s];
        __syncthreads();
    }
    if (tid == 0) out[0] = sm[0] * (1.0f / (float)BB);
}

extern "C" void kernel_launch(void* const* d_in, const int* in_sizes, int n_in,
                              void* d_out, int out_size)
{
    const float* em    = (const float*)d_in[0];
    const int*   tagw  = (const int*)  d_in[1];   // raw words; dtype detected on device
    const float* trans = (const float*)d_in[2];
    float* out = (float*)d_out;

    crf_main<<<BB, TT>>>(em, tagw, trans);
    crf_reduce<<<1, BB>>>(out);
}